// round 1
// baseline (speedup 1.0000x reference)
#include <cuda_runtime.h>
#include <float.h>

// SpatialAttention2D: out[b,c] = sum_hw x[b,c,hw] * softmax_hw(sum_c x[b,c,hw]*w[c] + bias)
// bias is a constant shift -> softmax-invariant -> never read.
//
// Strategy: one CTA per batch (B=64), 1024 threads (32 warps).
// HW=1024 processed in NCHUNK=8 chunks of S=128 positions.
// Phase A (per chunk): coalesced LDG.128 of the C x S tile, per-warp partial
//   score reduction over c, smem tree-reduce -> chunk scores.
// Online softmax update (warp 0): running max m, running Z, rescale factor.
// Phase B (per chunk): warp w owns c-rows [32w, 32w+32); each lane holds one
//   float4 (4 hw positions) per row; acc[ci] = acc[ci]*scale + dot(x4, p4).
//   Re-reads the exact bytes phase A just pulled -> L1/L2 hit, not DRAM.
// Final: butterfly-reduce the 32 per-lane partials per c, divide by Z, store.

#define BATCH     64
#define CCH       1024
#define HWN       1024
#define SCHUNK    128
#define NCHUNK    (HWN / SCHUNK)   // 8
#define NTHREADS  1024
#define NWARPS    32

__global__ __launch_bounds__(NTHREADS, 1)
void spatial_attn2d_kernel(const float* __restrict__ x,
                           const float* __restrict__ w,
                           float* __restrict__ out)
{
    __shared__ float s_w[CCH];                   // 4 KB   channel weights
    __shared__ float s_part[NWARPS * SCHUNK];    // 16 KB  per-warp score partials
    __shared__ float s_scores[SCHUNK];           // 512 B  chunk scores
    __shared__ float s_p[SCHUNK];                // 512 B  exp(s - m_new)
    __shared__ float s_scale;                    // rescale factor for this chunk
    __shared__ float s_Z;                        // final partition sum

    const int tid  = threadIdx.x;
    const int wid  = tid >> 5;
    const int lane = tid & 31;
    const int b    = blockIdx.x;

    // preload weights (exactly one element per thread)
    s_w[tid] = w[tid];
    __syncthreads();

    const float* xb = x + (size_t)b * CCH * HWN;
    // this warp's contiguous c-block base (used by BOTH phases -> L1 reuse)
    const float* xw = xb + (size_t)(wid * 32) * HWN;

    float m_run = -FLT_MAX;   // only warp 0's copy is meaningful
    float Z     = 0.0f;

    float acc[32];
    #pragma unroll
    for (int i = 0; i < 32; i++) acc[i] = 0.0f;

    for (int ch = 0; ch < NCHUNK; ch++) {
        const int base = ch * SCHUNK;

        // ---------------- Phase A: chunk scores ----------------
        // lane 'lane' handles hw positions base + 4*lane .. +3 (one float4),
        // warp 'wid' reduces over its 32 c-rows.
        {
            float4 ps = make_float4(0.f, 0.f, 0.f, 0.f);
            const float* pa = xw + base + lane * 4;
            #pragma unroll
            for (int k = 0; k < 32; k++) {
                float4 v = *(const float4*)(pa + (size_t)k * HWN);
                float wc = s_w[wid * 32 + k];       // smem broadcast
                ps.x = fmaf(v.x, wc, ps.x);
                ps.y = fmaf(v.y, wc, ps.y);
                ps.z = fmaf(v.z, wc, ps.z);
                ps.w = fmaf(v.w, wc, ps.w);
            }
            *(float4*)&s_part[wid * SCHUNK + lane * 4] = ps;
        }
        __syncthreads();

        // reduce partials over the 32 warps: threads 0..127, conflict-free LDS
        if (tid < SCHUNK) {
            float s = 0.0f;
            #pragma unroll
            for (int g = 0; g < NWARPS; g++) s += s_part[g * SCHUNK + tid];
            s_scores[tid] = s;
        }
        __syncthreads();

        // ---------------- Online softmax update (warp 0) ----------------
        if (wid == 0) {
            float v0 = s_scores[lane];
            float v1 = s_scores[lane + 32];
            float v2 = s_scores[lane + 64];
            float v3 = s_scores[lane + 96];
            float ml = fmaxf(fmaxf(v0, v1), fmaxf(v2, v3));
            #pragma unroll
            for (int o = 16; o; o >>= 1)
                ml = fmaxf(ml, __shfl_xor_sync(0xffffffffu, ml, o));
            float m_new = fmaxf(m_run, ml);
            float scale = __expf(m_run - m_new);
            float p0 = __expf(v0 - m_new);
            float p1 = __expf(v1 - m_new);
            float p2 = __expf(v2 - m_new);
            float p3 = __expf(v3 - m_new);
            s_p[lane]      = p0;
            s_p[lane + 32] = p1;
            s_p[lane + 64] = p2;
            s_p[lane + 96] = p3;
            float zc = p0 + p1 + p2 + p3;
            #pragma unroll
            for (int o = 16; o; o >>= 1)
                zc += __shfl_xor_sync(0xffffffffu, zc, o);
            Z = Z * scale + zc;
            m_run = m_new;
            if (lane == 0) s_scale = scale;
        }
        __syncthreads();

        // ---------------- Phase B: weighted accumulation ----------------
        // Same warp re-reads its own 32 c-rows, same chunk columns -> L1/L2 hit.
        {
            float scale = s_scale;
            float4 p4 = *(const float4*)&s_p[lane * 4];
            const float* pb = xw + base + lane * 4;
            #pragma unroll
            for (int ci = 0; ci < 32; ci++) {
                float4 v = *(const float4*)(pb + (size_t)ci * HWN);
                float d = v.x * p4.x + v.y * p4.y + v.z * p4.z + v.w * p4.w;
                acc[ci] = fmaf(acc[ci], scale, d);
            }
        }
        __syncthreads();   // protect s_part / s_p for the next chunk
    }

    if (tid == 0) s_Z = Z;
    __syncthreads();
    const float invZ = 1.0f / s_Z;

    // reduce the 32 per-lane partials for each of this warp's 32 channels
    float r = 0.0f;
    #pragma unroll
    for (int ci = 0; ci < 32; ci++) {
        float v = acc[ci];
        #pragma unroll
        for (int o = 16; o; o >>= 1)
            v += __shfl_xor_sync(0xffffffffu, v, o);
        if (lane == ci) r = v;
    }
    out[(size_t)b * CCH + wid * 32 + lane] = r * invZ;
}

extern "C" void kernel_launch(void* const* d_in, const int* in_sizes, int n_in,
                              void* d_out, int out_size)
{
    const float* x = (const float*)d_in[0];   // [64,1024,32,32]
    const float* w = (const float*)d_in[1];   // [1024]
    // d_in[2] = attn_b : softmax-invariant constant shift, intentionally unused
    float* out = (float*)d_out;               // [64,1024]

    spatial_attn2d_kernel<<<BATCH, NTHREADS>>>(x, w, out);
}

// round 2
// speedup vs baseline: 2.1865x; 2.1865x over previous
#include <cuda_runtime.h>
#include <float.h>

// SpatialAttention2D fused, full-chip version.
// out[b,c] = sum_hw x[b,c,hw] * softmax_hw( sum_c x[b,c,hw]*w[c] + bias )
// bias shifts every score equally -> softmax-invariant -> never read.
//
// Kernel 1: grid = B*G = 64*4 = 256 CTAs (one wave, ~2 CTAs/SM), 512 threads.
//   CTA (b,g) owns hw slice [g*256, (g+1)*256), processed in 16 sub-chunks of 16.
//   Per sub-chunk:
//     Phase A: each warp loads 64 c-rows x 16 hw (float4, coalesced 64B runs),
//              FMAs score partials in-flight, AND stashes the tile to padded
//              smem (row stride 20 floats -> conflict-free float4 access).
//     Online softmax (warp 0) over the 16 fresh scores: running m, Z, scale.
//     Phase B: thread t owns channels {t, t+512}; reads its 2 rows from the
//              SMEM stash (zero extra DRAM traffic), acc = acc*scale + dot(x,p).
//   End: partial (acc[c], m, Z) -> global scratch.
// Kernel 2: combines the G=4 partials per batch (log-sum-exp merge), writes out.

#define BATCH     64
#define CCH       1024
#define HWN       1024
#define GSPLIT    4
#define S_CTA     (HWN / GSPLIT)      // 256 hw positions per CTA
#define S2        16                  // sub-chunk positions
#define NSUB      (S_CTA / S2)        // 16
#define NTHREADS  512
#define NWARPS    16
#define ROWSTRIDE 20                  // stash row stride in floats (pad 16->20)

// smem layout (floats)
#define OFF_STASH 0
#define OFF_W     (CCH * ROWSTRIDE)            // 20480
#define OFF_PART  (OFF_W + CCH)                // 21504  (16 warps * stride 20)
#define OFF_P     (OFF_PART + NWARPS * 20)     // 21824
#define OFF_SCALE (OFF_P + 16)                 // 21840
#define SMEM_FLOATS (OFF_SCALE + 4)
#define SMEM_BYTES  (SMEM_FLOATS * 4)          // ~87.4 KB

// cross-CTA scratch (device globals: allowed, no allocation)
__device__ float  g_acc[BATCH * GSPLIT * CCH];   // 1 MB
__device__ float2 g_mz[BATCH * GSPLIT];

__global__ __launch_bounds__(NTHREADS, 2)
void spatial_attn2d_pass1(const float* __restrict__ x,
                          const float* __restrict__ w)
{
    extern __shared__ float sm[];
    float* stash  = sm + OFF_STASH;
    float* s_w    = sm + OFF_W;
    float* s_part = sm + OFF_PART;
    float* s_p    = sm + OFF_P;
    float* s_scl  = sm + OFF_SCALE;

    const int tid  = threadIdx.x;
    const int wid  = tid >> 5;
    const int lane = tid & 31;
    const int b    = blockIdx.x >> 2;
    const int g    = blockIdx.x & 3;

    // preload channel weights
    s_w[tid]       = w[tid];
    s_w[tid + 512] = w[tid + 512];
    __syncthreads();

    const float* xb = x + (size_t)b * CCH * HWN;
    const int hw0 = g * S_CTA;

    // phase-A addressing: warp owns 64 c-rows; lane: sub-row = lane>>2, j4 = (lane&3)*4
    const int sr  = lane >> 2;
    const int j4  = (lane & 3) * 4;

    float m_run = -FLT_MAX;   // meaningful in warp 0 only
    float Z     = 0.0f;
    float acc0  = 0.0f;       // channel tid
    float acc1  = 0.0f;       // channel tid + 512

    for (int ch = 0; ch < NSUB; ch++) {
        const int base = hw0 + ch * S2;

        // ---------- Phase A: load 64KB tile, score partials, smem stash ----------
        float4 ps = make_float4(0.f, 0.f, 0.f, 0.f);
        #pragma unroll
        for (int k = 0; k < 8; k++) {
            const int r = wid * 64 + k * 8 + sr;
            float4 v = *(const float4*)(xb + (size_t)r * HWN + base + j4);
            float wc = s_w[r];
            ps.x = fmaf(v.x, wc, ps.x);
            ps.y = fmaf(v.y, wc, ps.y);
            ps.z = fmaf(v.z, wc, ps.z);
            ps.w = fmaf(v.w, wc, ps.w);
            *(float4*)(stash + r * ROWSTRIDE + j4) = v;   // write-through stash
        }
        // reduce over lanes holding other rows (same j4): offsets 4,8,16
        #pragma unroll
        for (int o = 4; o <= 16; o <<= 1) {
            ps.x += __shfl_xor_sync(0xffffffffu, ps.x, o);
            ps.y += __shfl_xor_sync(0xffffffffu, ps.y, o);
            ps.z += __shfl_xor_sync(0xffffffffu, ps.z, o);
            ps.w += __shfl_xor_sync(0xffffffffu, ps.w, o);
        }
        if (lane < 4)
            *(float4*)(s_part + wid * 20 + j4) = ps;
        __syncthreads();

        // ---------- Online softmax update (warp 0, 16 positions) ----------
        if (wid == 0) {
            float s = -FLT_MAX;
            if (lane < S2) {
                s = 0.0f;
                #pragma unroll
                for (int ww = 0; ww < NWARPS; ww++) s += s_part[ww * 20 + lane];
            }
            float ml = s;
            #pragma unroll
            for (int o = 16; o; o >>= 1)
                ml = fmaxf(ml, __shfl_xor_sync(0xffffffffu, ml, o));
            float m_new = fmaxf(m_run, ml);
            float scale = __expf(m_run - m_new);
            float p = (lane < S2) ? __expf(s - m_new) : 0.0f;
            if (lane < S2) s_p[lane] = p;
            float zc = p;
            #pragma unroll
            for (int o = 16; o; o >>= 1)
                zc += __shfl_xor_sync(0xffffffffu, zc, o);
            Z = fmaf(Z, scale, zc);
            m_run = m_new;
            if (lane == 0) s_scl[0] = scale;
        }
        __syncthreads();

        // ---------- Phase B: weighted accumulation from SMEM stash ----------
        {
            const float scale = s_scl[0];
            float4 p0 = *(const float4*)(s_p + 0);    // broadcast loads
            float4 p1 = *(const float4*)(s_p + 4);
            float4 p2 = *(const float4*)(s_p + 8);
            float4 p3 = *(const float4*)(s_p + 12);

            const float* r0 = stash + tid * ROWSTRIDE;
            float4 a = *(const float4*)(r0 + 0);
            float4 bq = *(const float4*)(r0 + 4);
            float4 c = *(const float4*)(r0 + 8);
            float4 d = *(const float4*)(r0 + 12);
            float dot0 = a.x*p0.x + a.y*p0.y + a.z*p0.z + a.w*p0.w
                       + bq.x*p1.x + bq.y*p1.y + bq.z*p1.z + bq.w*p1.w
                       + c.x*p2.x + c.y*p2.y + c.z*p2.z + c.w*p2.w
                       + d.x*p3.x + d.y*p3.y + d.z*p3.z + d.w*p3.w;
            acc0 = fmaf(acc0, scale, dot0);

            const float* r1 = stash + (tid + 512) * ROWSTRIDE;
            a  = *(const float4*)(r1 + 0);
            bq = *(const float4*)(r1 + 4);
            c  = *(const float4*)(r1 + 8);
            d  = *(const float4*)(r1 + 12);
            float dot1 = a.x*p0.x + a.y*p0.y + a.z*p0.z + a.w*p0.w
                       + bq.x*p1.x + bq.y*p1.y + bq.z*p1.z + bq.w*p1.w
                       + c.x*p2.x + c.y*p2.y + c.z*p2.z + c.w*p2.w
                       + d.x*p3.x + d.y*p3.y + d.z*p3.z + d.w*p3.w;
            acc1 = fmaf(acc1, scale, dot1);
        }
        __syncthreads();   // protect stash/s_part/s_p before next sub-chunk
    }

    // ---------- emit partials ----------
    const int slot = blockIdx.x;
    g_acc[(size_t)slot * CCH + tid]       = acc0;
    g_acc[(size_t)slot * CCH + tid + 512] = acc1;
    if (tid == 0) g_mz[slot] = make_float2(m_run, Z);
}

__global__ __launch_bounds__(1024, 1)
void spatial_attn2d_pass2(float* __restrict__ out)
{
    const int b = blockIdx.x;
    const int t = threadIdx.x;

    float2 mz0 = g_mz[b * GSPLIT + 0];
    float2 mz1 = g_mz[b * GSPLIT + 1];
    float2 mz2 = g_mz[b * GSPLIT + 2];
    float2 mz3 = g_mz[b * GSPLIT + 3];
    float M = fmaxf(fmaxf(mz0.x, mz1.x), fmaxf(mz2.x, mz3.x));
    float e0 = __expf(mz0.x - M), e1 = __expf(mz1.x - M);
    float e2 = __expf(mz2.x - M), e3 = __expf(mz3.x - M);
    float denom = mz0.y * e0 + mz1.y * e1 + mz2.y * e2 + mz3.y * e3;

    const size_t base = (size_t)b * GSPLIT * CCH;
    float num = g_acc[base + 0 * CCH + t] * e0
              + g_acc[base + 1 * CCH + t] * e1
              + g_acc[base + 2 * CCH + t] * e2
              + g_acc[base + 3 * CCH + t] * e3;

    out[(size_t)b * CCH + t] = num / denom;
}

extern "C" void kernel_launch(void* const* d_in, const int* in_sizes, int n_in,
                              void* d_out, int out_size)
{
    const float* x = (const float*)d_in[0];   // [64,1024,32,32]
    const float* w = (const float*)d_in[1];   // [1024]
    // d_in[2] = attn_b : softmax-invariant, unused
    float* out = (float*)d_out;               // [64,1024]

    cudaFuncSetAttribute(spatial_attn2d_pass1,
                         cudaFuncAttributeMaxDynamicSharedMemorySize, SMEM_BYTES);
    spatial_attn2d_pass1<<<BATCH * GSPLIT, NTHREADS, SMEM_BYTES>>>(x, w);
    spatial_attn2d_pass2<<<BATCH, 1024>>>(out);
}

// round 4
// speedup vs baseline: 2.7513x; 1.2583x over previous
#include <cuda_runtime.h>
#include <float.h>

// SpatialAttention2D fused, register-resident version.
// out[b,c] = sum_hw x[b,c,hw] * softmax_hw( sum_c x[b,c,hw]*w[c] + bias )
// bias is softmax-invariant -> never read.
//
// Pass 1: grid = B*G = 64*8 = 512 CTAs, 512 threads (~3.5 waves at 1 CTA/SM).
//   CTA (b,g) owns 128 hw positions, 8 sub-chunks of 16.
//   Thread (wid,lane): sr = lane>>2, j4 = (lane&3)*4.
//   It owns rows r_k = wid*64 + k*8 + sr (k=0..7), cols [j4, j4+4) of each chunk.
//   Per sub-chunk:
//     - prefetch next tile into the other register buffer (LDG.128 x8, overlapped)
//     - scores: ps += v[k]*w[r_k]; shfl-reduce over sr; warp partials -> smem
//     - warp 0: online softmax (m, Z, scale, p[16])
//     - phase B: pj = p[j4..j4+3] (one broadcast LDS.128);
//                acc[k] = acc[k]*scale + dot(v[k], pj)   -- all registers!
//   End: combine acc over the 4 col-group lanes (2 shfls), partials -> scratch.
// Pass 2: log-sum-exp merge of the 8 partials per batch.

#define BATCH     64
#define CCH       1024
#define HWN       1024
#define GSPLIT    8
#define S_CTA     (HWN / GSPLIT)      // 128
#define S2        16
#define NSUB      (S_CTA / S2)        // 8
#define NTHREADS  512
#define NWARPS    16

__device__ float  g_acc[BATCH * GSPLIT * CCH];   // 2 MB scratch
__device__ float2 g_mz[BATCH * GSPLIT];

struct SM {
    float part[NWARPS * 20];   // per-warp score partials, stride 20 (conflict-free)
    float p[S2];               // exp(s - m_new)
    float scl;                 // rescale
    float outbuf[CCH];         // staging for coalesced scratch write
};

__global__ __launch_bounds__(NTHREADS)
void spatial_attn2d_pass1(const float* __restrict__ x,
                          const float* __restrict__ w)
{
    __shared__ SM sm;

    const int tid  = threadIdx.x;
    const int wid  = tid >> 5;
    const int lane = tid & 31;
    const int b    = blockIdx.x >> 3;
    const int g    = blockIdx.x & 7;

    const int sr = lane >> 2;          // 0..7  sub-row
    const int j4 = (lane & 3) * 4;     // 0,4,8,12  col group

    // per-thread base: row wid*64+sr, col offset j4, within batch b, slice g
    const float* pbase = x + (size_t)b * CCH * HWN
                           + (size_t)(wid * 64 + sr) * HWN
                           + g * S_CTA + j4;

    // channel weights for this thread's 8 rows
    float wc[8];
    #pragma unroll
    for (int k = 0; k < 8; k++)
        wc[k] = __ldg(w + wid * 64 + k * 8 + sr);

    float m_run = -FLT_MAX;   // warp 0 only
    float Z     = 0.0f;
    float acc[8];
    #pragma unroll
    for (int k = 0; k < 8; k++) acc[k] = 0.0f;

    float4 va[8], vb[8];

    // preload tile 0
    #pragma unroll
    for (int k = 0; k < 8; k++)
        va[k] = *(const float4*)(pbase + (size_t)k * 8 * HWN);

    #pragma unroll
    for (int ch = 0; ch < NSUB; ch++) {
        float4* cur = (ch & 1) ? vb : va;
        float4* nxt = (ch & 1) ? va : vb;

        // ---- prefetch next tile (overlaps everything below) ----
        if (ch + 1 < NSUB) {
            const float* pn = pbase + (ch + 1) * S2;
            #pragma unroll
            for (int k = 0; k < 8; k++)
                nxt[k] = *(const float4*)(pn + (size_t)k * 8 * HWN);
        }

        // ---- scores: reduce over this thread's 8 rows ----
        float4 ps = make_float4(0.f, 0.f, 0.f, 0.f);
        #pragma unroll
        for (int k = 0; k < 8; k++) {
            ps.x = fmaf(cur[k].x, wc[k], ps.x);
            ps.y = fmaf(cur[k].y, wc[k], ps.y);
            ps.z = fmaf(cur[k].z, wc[k], ps.z);
            ps.w = fmaf(cur[k].w, wc[k], ps.w);
        }
        // reduce over sr (lane bits 2..4), j4 lanes stay distinct
        #pragma unroll
        for (int o = 4; o <= 16; o <<= 1) {
            ps.x += __shfl_xor_sync(0xffffffffu, ps.x, o);
            ps.y += __shfl_xor_sync(0xffffffffu, ps.y, o);
            ps.z += __shfl_xor_sync(0xffffffffu, ps.z, o);
            ps.w += __shfl_xor_sync(0xffffffffu, ps.w, o);
        }
        if (lane < 4)
            *(float4*)(sm.part + wid * 20 + j4) = ps;
        __syncthreads();

        // ---- online softmax (warp 0) over 16 fresh scores ----
        if (wid == 0) {
            float s = -FLT_MAX;
            if (lane < S2) {
                s = 0.0f;
                #pragma unroll
                for (int ww = 0; ww < NWARPS; ww++)
                    s += sm.part[ww * 20 + lane];
            }
            float ml = s;
            #pragma unroll
            for (int o = 16; o; o >>= 1)
                ml = fmaxf(ml, __shfl_xor_sync(0xffffffffu, ml, o));
            float m_new = fmaxf(m_run, ml);
            float scale = __expf(m_run - m_new);
            float p = (lane < S2) ? __expf(s - m_new) : 0.0f;
            if (lane < S2) sm.p[lane] = p;
            float zc = p;
            #pragma unroll
            for (int o = 16; o; o >>= 1)
                zc += __shfl_xor_sync(0xffffffffu, zc, o);
            Z = fmaf(Z, scale, zc);
            m_run = m_new;
            if (lane == 0) sm.scl = scale;
        }
        __syncthreads();

        // ---- phase B: all-register weighted accumulation ----
        {
            const float scale = sm.scl;
            const float4 pj = *(const float4*)(sm.p + j4);   // broadcast LDS.128
            #pragma unroll
            for (int k = 0; k < 8; k++) {
                float d = cur[k].x * pj.x + cur[k].y * pj.y
                        + cur[k].z * pj.z + cur[k].w * pj.w;
                acc[k] = fmaf(acc[k], scale, d);
            }
        }
        __syncthreads();   // protect sm.part / sm.p for next sub-chunk
    }

    // ---- combine over the 4 col-group lanes, stage, write scratch ----
    #pragma unroll
    for (int k = 0; k < 8; k++) {
        float a = acc[k];
        a += __shfl_xor_sync(0xffffffffu, a, 1);
        a += __shfl_xor_sync(0xffffffffu, a, 2);
        if ((lane & 3) == 0)
            sm.outbuf[wid * 64 + k * 8 + sr] = a;
    }
    __syncthreads();

    const int slot = blockIdx.x;
    g_acc[(size_t)slot * CCH + tid]       = sm.outbuf[tid];
    g_acc[(size_t)slot * CCH + tid + 512] = sm.outbuf[tid + 512];
    if (tid == 0) g_mz[slot] = make_float2(m_run, Z);
}

__global__ __launch_bounds__(1024, 1)
void spatial_attn2d_pass2(float* __restrict__ out)
{
    const int b = blockIdx.x;
    const int t = threadIdx.x;

    float m[GSPLIT], z[GSPLIT];
    float M = -FLT_MAX;
    #pragma unroll
    for (int i = 0; i < GSPLIT; i++) {
        float2 mz = g_mz[b * GSPLIT + i];
        m[i] = mz.x; z[i] = mz.y;
        M = fmaxf(M, m[i]);
    }
    float denom = 0.0f, num = 0.0f;
    const size_t base = (size_t)b * GSPLIT * CCH;
    #pragma unroll
    for (int i = 0; i < GSPLIT; i++) {
        float e = __expf(m[i] - M);
        denom = fmaf(z[i], e, denom);
        num   = fmaf(g_acc[base + (size_t)i * CCH + t], e, num);
    }
    out[(size_t)b * CCH + t] = num / denom;
}

extern "C" void kernel_launch(void* const* d_in, const int* in_sizes, int n_in,
                              void* d_out, int out_size)
{
    const float* x = (const float*)d_in[0];   // [64,1024,32,32]
    const float* w = (const float*)d_in[1];   // [1024]
    // d_in[2] = attn_b : softmax-invariant, unused
    float* out = (float*)d_out;               // [64,1024]

    spatial_attn2d_pass1<<<BATCH * GSPLIT, NTHREADS>>>(x, w);
    spatial_attn2d_pass2<<<BATCH, 1024>>>(out);
}